// round 6
// baseline (speedup 1.0000x reference)
#include <cuda_runtime.h>
#include <cuda_bf16.h>

// Problem constants
#define NB    4096
#define LATD  64
#define GDIM  2016

// floats per sample group in k_main smem: 4 matrices + vectors + reduction
#define GRP_STRIDE (4 * 4096 + 256 + 32)   // 16672 floats
#define MAIN_SMEM_BYTES (3 * GRP_STRIDE * sizeof(float))

// Scratch for gi = gi_latent @ W_up^T + b_up   (33 MB)
__device__ float g_gi[NB * GDIM];

// ---------------------------------------------------------------------------
// packed f32x2 helpers (sm_100+)
// ---------------------------------------------------------------------------
__device__ __forceinline__ unsigned long long pack2(float x) {
    unsigned long long r;
    asm("mov.b64 %0, {%1, %1};" : "=l"(r) : "f"(x));
    return r;
}
__device__ __forceinline__ void fma2(unsigned long long& acc, unsigned long long a, unsigned long long b) {
    asm("fma.rn.f32x2 %0, %1, %2, %0;" : "+l"(acc) : "l"(a), "l"(b));
}
__device__ __forceinline__ float2 unpack2(unsigned long long v) {
    float2 f;
    asm("mov.b64 {%0, %1}, %2;" : "=f"(f.x), "=f"(f.y) : "l"(v));
    return f;
}

// group-local barrier: 64 threads of group (threadIdx.x>>6) via named barrier
__device__ __forceinline__ void gbar() {
    asm volatile("bar.sync %0, 64;" :: "r"((int)(threadIdx.x >> 6) + 1) : "memory");
}

// ---------------------------------------------------------------------------
// Core 64x64x64 matmul on group smem, 64 threads, 8x8 register tile/thread.
// OUT = s*(X @ Y) + a*X ; OUT may alias X and/or Y (writes after barrier).
// ---------------------------------------------------------------------------
__device__ __noinline__ void mm_step(const float* X, const float* Y, float* OUT,
                                     float a, float s) {
    const int lt  = threadIdx.x & 63;
    const int tx8 = (lt & 7) * 8;
    const int ty8 = (lt >> 3) * 8;

    unsigned long long acc[8][4];
#pragma unroll
    for (int r = 0; r < 8; r++)
#pragma unroll
        for (int c = 0; c < 4; c++) acc[r][c] = 0ull;

    const float* Xp = X + ty8 * 64;
    const float* Yp = Y + tx8;

#pragma unroll 2
    for (int k4 = 0; k4 < 16; k4++) {
        float4 xv[8];
#pragma unroll
        for (int r = 0; r < 8; r++)
            xv[r] = *reinterpret_cast<const float4*>(Xp + r * 64 + k4 * 4);
#pragma unroll
        for (int kk = 0; kk < 4; kk++) {
            const float* yrow = Yp + (k4 * 4 + kk) * 64;
            ulonglong2 y0 = *reinterpret_cast<const ulonglong2*>(yrow);
            ulonglong2 y1 = *reinterpret_cast<const ulonglong2*>(yrow + 4);
#pragma unroll
            for (int r = 0; r < 8; r++) {
                unsigned long long xx = pack2(reinterpret_cast<const float*>(&xv[r])[kk]);
                fma2(acc[r][0], xx, y0.x);
                fma2(acc[r][1], xx, y0.y);
                fma2(acc[r][2], xx, y1.x);
                fma2(acc[r][3], xx, y1.y);
            }
        }
    }

    // epilogue: res = s*acc + a*X[i][j]  (read X before barrier; OUT may alias)
    float res[8][8];
#pragma unroll
    for (int r = 0; r < 8; r++) {
        float4 x0 = *reinterpret_cast<const float4*>(X + (ty8 + r) * 64 + tx8);
        float4 x1 = *reinterpret_cast<const float4*>(X + (ty8 + r) * 64 + tx8 + 4);
        float2 p0 = unpack2(acc[r][0]);
        float2 p1 = unpack2(acc[r][1]);
        float2 p2 = unpack2(acc[r][2]);
        float2 p3 = unpack2(acc[r][3]);
        res[r][0] = s * p0.x + a * x0.x;
        res[r][1] = s * p0.y + a * x0.y;
        res[r][2] = s * p1.x + a * x0.z;
        res[r][3] = s * p1.y + a * x0.w;
        res[r][4] = s * p2.x + a * x1.x;
        res[r][5] = s * p2.y + a * x1.y;
        res[r][6] = s * p3.x + a * x1.z;
        res[r][7] = s * p3.y + a * x1.w;
    }
    gbar();
#pragma unroll
    for (int r = 0; r < 8; r++) {
        *reinterpret_cast<float4*>(OUT + (ty8 + r) * 64 + tx8) =
            make_float4(res[r][0], res[r][1], res[r][2], res[r][3]);
        *reinterpret_cast<float4*>(OUT + (ty8 + r) * 64 + tx8 + 4) =
            make_float4(res[r][4], res[r][5], res[r][6], res[r][7]);
    }
    gbar();
}

// ---------------------------------------------------------------------------
// Kernel 1: gi = gi_latent @ W_up^T + b_up
// 64 threads per block, 64x64 output tile, 8x8 register tile per thread.
// ---------------------------------------------------------------------------
__global__ __launch_bounds__(64) void k_up(const float* __restrict__ gi_latent,
                                           const float* __restrict__ W_up,
                                           const float* __restrict__ b_up) {
    __shared__ float sA[64 * 64];   // [sample][k]
    __shared__ float sWt[64 * 64];  // [k][g]  (transposed W tile)
    const int s0 = blockIdx.y * 64;
    const int g0 = blockIdx.x * 64;
    const int t  = threadIdx.x;     // 0..63

    const float4* Ag = reinterpret_cast<const float4*>(gi_latent + s0 * 64);
#pragma unroll
    for (int q = 0; q < 16; q++) {
        int e = t + q * 64;
        reinterpret_cast<float4*>(sA)[e] = Ag[e];
    }
#pragma unroll
    for (int q = 0; q < 16; q++) {
        int e   = t + q * 64;
        int row = e >> 4;
        int c4  = e & 15;
        int g   = g0 + row;
        float4 v = make_float4(0.f, 0.f, 0.f, 0.f);
        if (g < GDIM) v = reinterpret_cast<const float4*>(W_up + g * 64)[c4];
        sWt[(c4 * 4 + 0) * 64 + row] = v.x;
        sWt[(c4 * 4 + 1) * 64 + row] = v.y;
        sWt[(c4 * 4 + 2) * 64 + row] = v.z;
        sWt[(c4 * 4 + 3) * 64 + row] = v.w;
    }
    __syncthreads();

    const int tx8 = (t & 7) * 8;
    const int ty8 = (t >> 3) * 8;

    unsigned long long acc[8][4];
#pragma unroll
    for (int r = 0; r < 8; r++)
#pragma unroll
        for (int c = 0; c < 4; c++) acc[r][c] = 0ull;

    const float* Xp = sA + ty8 * 64;
    const float* Yp = sWt + tx8;

#pragma unroll 2
    for (int k4 = 0; k4 < 16; k4++) {
        float4 xv[8];
#pragma unroll
        for (int r = 0; r < 8; r++)
            xv[r] = *reinterpret_cast<const float4*>(Xp + r * 64 + k4 * 4);
#pragma unroll
        for (int kk = 0; kk < 4; kk++) {
            const float* yrow = Yp + (k4 * 4 + kk) * 64;
            ulonglong2 y0 = *reinterpret_cast<const ulonglong2*>(yrow);
            ulonglong2 y1 = *reinterpret_cast<const ulonglong2*>(yrow + 4);
#pragma unroll
            for (int r = 0; r < 8; r++) {
                unsigned long long xx = pack2(reinterpret_cast<const float*>(&xv[r])[kk]);
                fma2(acc[r][0], xx, y0.x);
                fma2(acc[r][1], xx, y0.y);
                fma2(acc[r][2], xx, y1.x);
                fma2(acc[r][3], xx, y1.y);
            }
        }
    }

    if (g0 + tx8 < GDIM) {
        float bb[8];
#pragma unroll
        for (int c = 0; c < 8; c++) bb[c] = b_up[g0 + tx8 + c];
#pragma unroll
        for (int r = 0; r < 8; r++) {
            float2 p0 = unpack2(acc[r][0]);
            float2 p1 = unpack2(acc[r][1]);
            float2 p2 = unpack2(acc[r][2]);
            float2 p3 = unpack2(acc[r][3]);
            float* o = g_gi + (size_t)(s0 + ty8 + r) * GDIM + g0 + tx8;
            *reinterpret_cast<float4*>(o) =
                make_float4(p0.x + bb[0], p0.y + bb[1], p1.x + bb[2], p1.y + bb[3]);
            *reinterpret_cast<float4*>(o + 4) =
                make_float4(p2.x + bb[4], p2.y + bb[5], p3.x + bb[6], p3.y + bb[7]);
        }
    }
}

// ---------------------------------------------------------------------------
// Kernel 2: 3 samples per 192-thread CTA (3 independent 64-thread groups with
// group-local named barriers so warps cover all 4 SMSPs).
// ---------------------------------------------------------------------------
__global__ __launch_bounds__(192, 1) void k_main(
    const float* __restrict__ li_latent,
    const float* __restrict__ W1, const float* __restrict__ b1,
    const float* __restrict__ W2, const float* __restrict__ b2,
    const float* __restrict__ W3, const float* __restrict__ b3,
    const float* __restrict__ W4, const float* __restrict__ b4,
    const float* __restrict__ W5, const float* __restrict__ b5,
    const float* __restrict__ W6, const float* __restrict__ b6,
    float* __restrict__ out) {
    extern __shared__ float smem[];
    const int g  = threadIdx.x >> 6;
    const int lt = threadIdx.x & 63;
    const int n  = blockIdx.x * 3 + g;
    if (n >= NB) return;

    float* base = smem + g * GRP_STRIDE;
    float* sB   = base;               // 4096
    float* sZ   = base + 4096;        // 4096
    float* sP   = base + 8192;        // 4096
    float* sU   = base + 12288;       // 4096
    float* sv   = base + 16384;       // 256 small vectors
    float* sred = base + 16384 + 256; // reduction scratch

    const float* gi = g_gi + (size_t)n * GDIM;

    // ---- build B = I - (A^T - A), A lower-tri from gi ----
    for (int e = lt; e < GDIM; e += 64) {
        int i = (int)((1.0f + sqrtf(1.0f + 8.0f * (float)e)) * 0.5f);
        while (i * (i - 1) / 2 > e) i--;
        while ((i + 1) * i / 2 <= e) i++;
        int j   = e - i * (i - 1) / 2;
        float v = gi[e];
        sB[i * 64 + j] = v;    // i > j
        sB[j * 64 + i] = -v;
    }
    sB[lt * 65] = 1.0f;
    gbar();

    // ---- norms = sum(|B|) * max(|B|), Z0 = B^T / norms ----
    float lsum = 0.f, lmax = 0.f;
#pragma unroll
    for (int q = 0; q < 16; q++) {
        float4 v = reinterpret_cast<const float4*>(sB)[lt * 16 + q];
        lsum += fabsf(v.x) + fabsf(v.y) + fabsf(v.z) + fabsf(v.w);
        lmax = fmaxf(lmax, fmaxf(fmaxf(fabsf(v.x), fabsf(v.y)),
                                 fmaxf(fabsf(v.z), fabsf(v.w))));
    }
#pragma unroll
    for (int o = 16; o; o >>= 1) {
        lsum += __shfl_xor_sync(0xFFFFFFFFu, lsum, o);
        lmax = fmaxf(lmax, __shfl_xor_sync(0xFFFFFFFFu, lmax, o));
    }
    if ((lt & 31) == 0) { sred[lt >> 5] = lsum; sred[2 + (lt >> 5)] = lmax; }
    gbar();
    if (lt == 0) {
        float S = sred[0] + sred[1];
        float M = fmaxf(sred[2], sred[3]);
        sred[4] = 1.0f / (S * M);
    }
    gbar();
    const float invn = sred[4];
    // Z0 row lt = column lt of B, scaled
    for (int j4 = 0; j4 < 16; j4++) {
        float4 v;
        v.x = sB[(j4 * 4 + 0) * 64 + lt] * invn;
        v.y = sB[(j4 * 4 + 1) * 64 + lt] * invn;
        v.z = sB[(j4 * 4 + 2) * 64 + lt] * invn;
        v.w = sB[(j4 * 4 + 3) * 64 + lt] * invn;
        *reinterpret_cast<float4*>(sZ + lt * 64 + j4 * 4) = v;
    }
    gbar();

    // ---- 10 Newton-Schulz iterations ----
#pragma unroll 1
    for (int it = 0; it < 10; it++) {
        mm_step(sB, sZ, sP, 0.0f, 1.0f);     // P  = B@Z
        mm_step(sP, sP, sU, 7.0f, -1.0f);    // U  = 7P - P@P
        mm_step(sP, sU, sU, 15.0f, -1.0f);   // U  = 15P - P@U
        mm_step(sZ, sU, sZ, 3.25f, -0.25f);  // Z  = 0.25*(13Z - Z@U)
    }
    // R = Z @ (2I - B) = 2Z - Z@B   -> stored in sP
    mm_step(sZ, sB, sP, 2.0f, -1.0f);
    const float* R = sP;

    // ---- MLP tail (64 threads, one output element each) ----
    sv[lt] = li_latent[n * 64 + lt];
    gbar();

    // mis[j] = sum_i R[i][j] * li[i]
    {
        float acc = 0.f;
        for (int i = 0; i < 64; i++) acc += R[i * 64 + lt] * sv[i];
        sv[64 + lt] = acc;
    }
    gbar();
    // h = relu(mis @ W1^T + b1)
    {
        float acc = b1[lt];
        const float* w = W1 + lt * 64;
        for (int k = 0; k < 64; k++) acc += sv[64 + k] * w[k];
        sv[128 + lt] = fmaxf(acc, 0.f);
    }
    gbar();
    // fc2 = h @ W2^T + b2
    {
        float acc = b2[lt];
        const float* w = W2 + lt * 64;
        for (int k = 0; k < 64; k++) acc += sv[128 + k] * w[k];
        sv[192 + lt] = acc;
    }
    gbar();
    // latent[i] = sum_j R[i][j] * fc2[j]
    {
        float acc = 0.f;
        for (int jj = 0; jj < 64; jj++) {
            int j = (lt + jj) & 63;
            acc += R[lt * 64 + j] * sv[192 + j];
        }
        sv[64 + lt] = acc;                       // latent (overwrites mis)
        out[262144 + 8192 + n * 64 + lt] = acc;  // latent output
    }
    gbar();
    // t3 = relu(latent @ W3^T + b3)
    {
        float acc = b3[lt];
        const float* w = W3 + lt * 64;
        for (int k = 0; k < 64; k++) acc += sv[64 + k] * w[k];
        sv[128 + lt] = fmaxf(acc, 0.f);
    }
    gbar();
    // recons = t3 @ W4^T + b4 ; t5 = relu(latent @ W5^T + b5)
    {
        float acc = b4[lt];
        const float* w = W4 + lt * 64;
        for (int j = 0; j < 64; j++) acc += sv[128 + j] * w[j];
        out[n * 64 + lt] = acc;                  // recons output

        float acc5 = b5[lt];
        const float* w5 = W5 + lt * 64;
        for (int k = 0; k < 64; k++) acc5 += sv[64 + k] * w5[k];
        sv[192 + lt] = fmaxf(acc5, 0.f);         // t5 (overwrites fc2)
    }
    gbar();
    // pred = t5 @ W6^T + b6   (2 outputs)
    if (lt < 2) {
        float acc = b6[lt];
        const float* w = W6 + lt * 64;
        for (int j = 0; j < 64; j++) acc += sv[192 + j] * w[j];
        out[262144 + n * 2 + lt] = acc;          // pred output
    }
}

// ---------------------------------------------------------------------------
// launch
// ---------------------------------------------------------------------------
extern "C" void kernel_launch(void* const* d_in, const int* in_sizes, int n_in,
                              void* d_out, int out_size) {
    const float* li    = (const float*)d_in[0];
    const float* gl    = (const float*)d_in[1];
    const float* W_up  = (const float*)d_in[2];
    const float* b_up  = (const float*)d_in[3];
    const float* W1    = (const float*)d_in[4];
    const float* b1    = (const float*)d_in[5];
    const float* W2    = (const float*)d_in[6];
    const float* b2    = (const float*)d_in[7];
    const float* W3    = (const float*)d_in[8];
    const float* b3    = (const float*)d_in[9];
    const float* W4    = (const float*)d_in[10];
    const float* b4    = (const float*)d_in[11];
    const float* W5    = (const float*)d_in[12];
    const float* b5    = (const float*)d_in[13];
    const float* W6    = (const float*)d_in[14];
    const float* b6    = (const float*)d_in[15];
    float* out = (float*)d_out;

    cudaFuncSetAttribute(k_main, cudaFuncAttributeMaxDynamicSharedMemorySize,
                         (int)MAIN_SMEM_BYTES);

    k_up<<<dim3((GDIM + 63) / 64, NB / 64), 64>>>(gl, W_up, b_up);
    k_main<<<(NB + 2) / 3, 192, MAIN_SMEM_BYTES>>>(li, W1, b1, W2, b2, W3, b3,
                                                   W4, b4, W5, b5, W6, b6, out);
}

// round 8
// speedup vs baseline: 2.1747x; 2.1747x over previous
#include <cuda_runtime.h>
#include <cuda_bf16.h>

// Problem constants
#define NB    4096
#define GDIM  2016
#define S     68            // padded row stride (floats) for 64x64 matrices
#define MS    (64 * S)      // floats per matrix (4352)

// smem: 4 matrices + vectors(256) + reduction(32)
#define MAIN_SMEM_FLOATS (4 * MS + 256 + 32)
#define MAIN_SMEM_BYTES  (MAIN_SMEM_FLOATS * sizeof(float))

// Scratch for gi = gi_latent @ W_up^T + b_up   (33 MB)
__device__ float g_gi[NB * GDIM];

// ---------------------------------------------------------------------------
// packed f32x2 helpers (fp32 SIMT path)
// ---------------------------------------------------------------------------
__device__ __forceinline__ unsigned long long pack2(float x) {
    unsigned long long r;
    asm("mov.b64 %0, {%1, %1};" : "=l"(r) : "f"(x));
    return r;
}
__device__ __forceinline__ void fma2(unsigned long long& acc, unsigned long long a, unsigned long long b) {
    asm("fma.rn.f32x2 %0, %1, %2, %0;" : "+l"(acc) : "l"(a), "l"(b));
}
__device__ __forceinline__ float2 unpack2(unsigned long long v) {
    float2 f;
    asm("mov.b64 {%0, %1}, %2;" : "=f"(f.x), "=f"(f.y) : "l"(v));
    return f;
}

// ---------------------------------------------------------------------------
// tf32 warp MMA: D += A(16x8) @ B(8x8)
// ---------------------------------------------------------------------------
__device__ __forceinline__ void mma_tf32(float* c, unsigned a0, unsigned a1,
                                         unsigned a2, unsigned a3,
                                         unsigned b0, unsigned b1) {
    asm volatile(
        "mma.sync.aligned.m16n8k8.row.col.f32.tf32.tf32.f32 "
        "{%0,%1,%2,%3}, {%4,%5,%6,%7}, {%8,%9}, {%0,%1,%2,%3};"
        : "+f"(c[0]), "+f"(c[1]), "+f"(c[2]), "+f"(c[3])
        : "r"(a0), "r"(a1), "r"(a2), "r"(a3), "r"(b0), "r"(b1));
}

// ---------------------------------------------------------------------------
// OUT = s*(X @ Y) + a*X via tensor cores (tf32 truncation of operands).
// 128 threads = 4 warps; warp w owns a 32x32 tile (2x2 warp grid).
// X, Y, OUT: 64x64, row stride S, in smem. OUT may alias X/Y (write after bar).
// ---------------------------------------------------------------------------
__device__ __noinline__ void mm_tf32_step(const float* X, const float* Y,
                                          float* OUT, float a, float s) {
    const int t    = threadIdx.x;
    const int lane = t & 31;
    const int w    = t >> 5;
    const int gid  = lane >> 2;   // 0..7
    const int tig  = lane & 3;    // 0..3
    const int wm   = (w >> 1) * 32;
    const int wn   = (w & 1) * 32;

    float acc[2][4][4];
#pragma unroll
    for (int mt = 0; mt < 2; mt++)
#pragma unroll
        for (int nt = 0; nt < 4; nt++)
#pragma unroll
            for (int q = 0; q < 4; q++) acc[mt][nt][q] = 0.f;

#pragma unroll
    for (int ks = 0; ks < 8; ks++) {
        const int k0 = ks * 8;
        unsigned af[2][4];
#pragma unroll
        for (int mt = 0; mt < 2; mt++) {
            const float* ap = X + (wm + 16 * mt + gid) * S + k0 + tig;
            af[mt][0] = __float_as_uint(ap[0]);
            af[mt][1] = __float_as_uint(ap[8 * S]);
            af[mt][2] = __float_as_uint(ap[4]);
            af[mt][3] = __float_as_uint(ap[8 * S + 4]);
        }
        unsigned bf[4][2];
#pragma unroll
        for (int nt = 0; nt < 4; nt++) {
            const float* bp = Y + (k0 + tig) * S + wn + 8 * nt + gid;
            bf[nt][0] = __float_as_uint(bp[0]);
            bf[nt][1] = __float_as_uint(bp[4 * S]);
        }
#pragma unroll
        for (int mt = 0; mt < 2; mt++)
#pragma unroll
            for (int nt = 0; nt < 4; nt++)
                mma_tf32(acc[mt][nt], af[mt][0], af[mt][1], af[mt][2], af[mt][3],
                         bf[nt][0], bf[nt][1]);
    }

    // epilogue: res = s*acc + a*X at the C-fragment positions
    float res[2][4][4];
#pragma unroll
    for (int mt = 0; mt < 2; mt++) {
        const int row = wm + 16 * mt + gid;
#pragma unroll
        for (int nt = 0; nt < 4; nt++) {
            const int col = wn + 8 * nt + 2 * tig;
            float2 x0 = *reinterpret_cast<const float2*>(X + row * S + col);
            float2 x1 = *reinterpret_cast<const float2*>(X + (row + 8) * S + col);
            res[mt][nt][0] = s * acc[mt][nt][0] + a * x0.x;
            res[mt][nt][1] = s * acc[mt][nt][1] + a * x0.y;
            res[mt][nt][2] = s * acc[mt][nt][2] + a * x1.x;
            res[mt][nt][3] = s * acc[mt][nt][3] + a * x1.y;
        }
    }
    __syncthreads();
#pragma unroll
    for (int mt = 0; mt < 2; mt++) {
        const int row = wm + 16 * mt + gid;
#pragma unroll
        for (int nt = 0; nt < 4; nt++) {
            const int col = wn + 8 * nt + 2 * tig;
            *reinterpret_cast<float2*>(OUT + row * S + col) =
                make_float2(res[mt][nt][0], res[mt][nt][1]);
            *reinterpret_cast<float2*>(OUT + (row + 8) * S + col) =
                make_float2(res[mt][nt][2], res[mt][nt][3]);
        }
    }
    __syncthreads();
}

// ---------------------------------------------------------------------------
// OUT = s*(X @ Y) + a*X in full fp32 (SIMT, packed f32x2).
// 128 threads, 8 rows x 4 cols per thread.
// ---------------------------------------------------------------------------
__device__ __noinline__ void mm_f32_step(const float* X, const float* Y,
                                         float* OUT, float a, float s) {
    const int t   = threadIdx.x;
    const int tx4 = (t & 15) * 4;   // col base
    const int ty8 = (t >> 4) * 8;   // row base

    unsigned long long acc[8][2];
#pragma unroll
    for (int r = 0; r < 8; r++) { acc[r][0] = 0ull; acc[r][1] = 0ull; }

    const float* Xp = X + ty8 * S;
    const float* Yp = Y + tx4;

#pragma unroll 4
    for (int k4 = 0; k4 < 16; k4++) {
        float4 xv[8];
#pragma unroll
        for (int r = 0; r < 8; r++)
            xv[r] = *reinterpret_cast<const float4*>(Xp + r * S + k4 * 4);
#pragma unroll
        for (int kk = 0; kk < 4; kk++) {
            ulonglong2 y = *reinterpret_cast<const ulonglong2*>(Yp + (k4 * 4 + kk) * S);
#pragma unroll
            for (int r = 0; r < 8; r++) {
                unsigned long long xx = pack2(reinterpret_cast<const float*>(&xv[r])[kk]);
                fma2(acc[r][0], xx, y.x);
                fma2(acc[r][1], xx, y.y);
            }
        }
    }

    float res[8][4];
#pragma unroll
    for (int r = 0; r < 8; r++) {
        float4 xr = *reinterpret_cast<const float4*>(X + (ty8 + r) * S + tx4);
        float2 p0 = unpack2(acc[r][0]);
        float2 p1 = unpack2(acc[r][1]);
        res[r][0] = s * p0.x + a * xr.x;
        res[r][1] = s * p0.y + a * xr.y;
        res[r][2] = s * p1.x + a * xr.z;
        res[r][3] = s * p1.y + a * xr.w;
    }
    __syncthreads();
#pragma unroll
    for (int r = 0; r < 8; r++)
        *reinterpret_cast<float4*>(OUT + (ty8 + r) * S + tx4) =
            make_float4(res[r][0], res[r][1], res[r][2], res[r][3]);
    __syncthreads();
}

// ---------------------------------------------------------------------------
// Kernel 1: gi = gi_latent @ W_up^T + b_up  (proven R2 config: 256 thr, 4x4)
// ---------------------------------------------------------------------------
__global__ __launch_bounds__(256) void k_up(const float* __restrict__ gi_latent,
                                            const float* __restrict__ W_up,
                                            const float* __restrict__ b_up) {
    __shared__ float sA[64 * 64];
    __shared__ float sW[64 * 64];
    const int s0 = blockIdx.y * 64;
    const int g0 = blockIdx.x * 64;
    const int t  = threadIdx.x;

    const float4* Ag = reinterpret_cast<const float4*>(gi_latent + s0 * 64);
#pragma unroll
    for (int q = 0; q < 4; q++) {
        int e = t + q * 256;
        reinterpret_cast<float4*>(sA)[e] = Ag[e];
    }
#pragma unroll
    for (int q = 0; q < 4; q++) {
        int e   = t + q * 256;
        int row = e >> 4;
        int c4  = e & 15;
        int g   = g0 + row;
        float4 v = make_float4(0.f, 0.f, 0.f, 0.f);
        if (g < GDIM) v = reinterpret_cast<const float4*>(W_up + g * 64)[c4];
        reinterpret_cast<float4*>(sW)[e] = v;
    }
    __syncthreads();

    const int tx4 = (t & 15) * 4;
    const int ty4 = (t >> 4) * 4;
    float acc[4][4];
#pragma unroll
    for (int r = 0; r < 4; r++)
#pragma unroll
        for (int c = 0; c < 4; c++) acc[r][c] = 0.f;

#pragma unroll 8
    for (int k = 0; k < 64; k++) {
        float xv[4], wv[4];
#pragma unroll
        for (int r = 0; r < 4; r++) xv[r] = sA[(ty4 + r) * 64 + k];
#pragma unroll
        for (int c = 0; c < 4; c++) wv[c] = sW[(tx4 + c) * 64 + k];
#pragma unroll
        for (int r = 0; r < 4; r++)
#pragma unroll
            for (int c = 0; c < 4; c++) acc[r][c] += xv[r] * wv[c];
    }

#pragma unroll
    for (int r = 0; r < 4; r++)
#pragma unroll
        for (int c = 0; c < 4; c++) {
            int g = g0 + tx4 + c;
            if (g < GDIM) g_gi[(size_t)(s0 + ty4 + r) * GDIM + g] = acc[r][c] + b_up[g];
        }
}

// ---------------------------------------------------------------------------
// Kernel 2: per-sample Cayley map + MLP tail. 1 sample per 128-thread CTA.
// 9 NS iterations on tensor cores (tf32) + 1 NS iteration + R in fp32 SIMT
// (fp32 cleanup contracts the tf32 noise quadratically -> fp32-level result).
// ---------------------------------------------------------------------------
__global__ __launch_bounds__(128) void k_main(
    const float* __restrict__ li_latent,
    const float* __restrict__ W1, const float* __restrict__ b1,
    const float* __restrict__ W2, const float* __restrict__ b2,
    const float* __restrict__ W3, const float* __restrict__ b3,
    const float* __restrict__ W4, const float* __restrict__ b4,
    const float* __restrict__ W5, const float* __restrict__ b5,
    const float* __restrict__ W6, const float* __restrict__ b6,
    float* __restrict__ out) {
    extern __shared__ float smem[];
    float* sB   = smem;               // 64 x S
    float* sZ   = smem + MS;
    float* sP   = smem + 2 * MS;
    float* sU   = smem + 3 * MS;
    float* sv   = smem + 4 * MS;      // 256 small vectors
    float* sred = smem + 4 * MS + 256;

    const int n = blockIdx.x;
    const int t = threadIdx.x;        // 0..127
    const float* gi = g_gi + (size_t)n * GDIM;

    // ---- build B = I - (A^T - A), A lower-tri from gi ----
    for (int e = t; e < GDIM; e += 128) {
        int i = (int)((1.0f + sqrtf(1.0f + 8.0f * (float)e)) * 0.5f);
        while (i * (i - 1) / 2 > e) i--;
        while ((i + 1) * i / 2 <= e) i++;
        int j   = e - i * (i - 1) / 2;
        float v = gi[e];
        sB[i * S + j] = v;    // i > j
        sB[j * S + i] = -v;
    }
    if (t < 64) sB[t * S + t] = 1.0f;
    __syncthreads();

    // ---- norms = sum(|B|) * max(|B|) over the 64x64 block (skip padding) ----
    {
        const int r  = t >> 1;
        const int c0 = (t & 1) * 32;
        float lsum = 0.f, lmax = 0.f;
#pragma unroll
        for (int q = 0; q < 8; q++) {
            float4 v = *reinterpret_cast<const float4*>(sB + r * S + c0 + q * 4);
            lsum += fabsf(v.x) + fabsf(v.y) + fabsf(v.z) + fabsf(v.w);
            lmax = fmaxf(lmax, fmaxf(fmaxf(fabsf(v.x), fabsf(v.y)),
                                     fmaxf(fabsf(v.z), fabsf(v.w))));
        }
#pragma unroll
        for (int o = 16; o; o >>= 1) {
            lsum += __shfl_xor_sync(0xFFFFFFFFu, lsum, o);
            lmax = fmaxf(lmax, __shfl_xor_sync(0xFFFFFFFFu, lmax, o));
        }
        if ((t & 31) == 0) { sred[t >> 5] = lsum; sred[4 + (t >> 5)] = lmax; }
    }
    __syncthreads();
    if (t == 0) {
        float Sm = sred[0] + sred[1] + sred[2] + sred[3];
        float Mx = fmaxf(fmaxf(sred[4], sred[5]), fmaxf(sred[6], sred[7]));
        sred[8] = 1.0f / (Sm * Mx);
    }
    __syncthreads();
    const float invn = sred[8];
    // Z0 = B^T * invn
    {
        const int r  = t >> 1;
        const int c0 = (t & 1) * 32;
        for (int c = c0; c < c0 + 32; c++)
            sZ[r * S + c] = sB[c * S + r] * invn;
    }
    __syncthreads();

    // ---- 9 tf32 Newton-Schulz iterations on tensor cores ----
#pragma unroll 1
    for (int it = 0; it < 9; it++) {
        mm_tf32_step(sB, sZ, sP, 0.0f, 1.0f);     // P = B@Z
        mm_tf32_step(sP, sP, sU, 7.0f, -1.0f);    // U = 7P - P@P
        mm_tf32_step(sP, sU, sU, 15.0f, -1.0f);   // U = 15P - P@U
        mm_tf32_step(sZ, sU, sZ, 3.25f, -0.25f);  // Z = 0.25*(13Z - Z@U)
    }
    // ---- final NS iteration + R in fp32 (cleanup) ----
    mm_f32_step(sB, sZ, sP, 0.0f, 1.0f);
    mm_f32_step(sP, sP, sU, 7.0f, -1.0f);
    mm_f32_step(sP, sU, sU, 15.0f, -1.0f);
    mm_f32_step(sZ, sU, sZ, 3.25f, -0.25f);
    // R = 2Z - Z@B  -> sP
    mm_f32_step(sZ, sB, sP, 2.0f, -1.0f);
    const float* R = sP;

    // ---- MLP tail (threads 0..63; all threads hit the barriers) ----
    if (t < 64) sv[t] = li_latent[n * 64 + t];
    __syncthreads();

    if (t < 64) {  // mis[j] = sum_i R[i][j] * li[i]
        float acc = 0.f;
        for (int i = 0; i < 64; i++) acc += R[i * S + t] * sv[i];
        sv[64 + t] = acc;
    }
    __syncthreads();
    if (t < 64) {  // h = relu(mis @ W1^T + b1)
        float acc = b1[t];
        const float* w = W1 + t * 64;
        for (int k = 0; k < 64; k++) acc += sv[64 + k] * w[k];
        sv[128 + t] = fmaxf(acc, 0.f);
    }
    __syncthreads();
    if (t < 64) {  // fc2 = h @ W2^T + b2
        float acc = b2[t];
        const float* w = W2 + t * 64;
        for (int k = 0; k < 64; k++) acc += sv[128 + k] * w[k];
        sv[192 + t] = acc;
    }
    __syncthreads();
    if (t < 64) {  // latent[i] = sum_j R[i][j] * fc2[j]
        float acc = 0.f;
        for (int jj = 0; jj < 64; jj++) {
            int j = (t + jj) & 63;
            acc += R[t * S + j] * sv[192 + j];
        }
        sv[64 + t] = acc;                       // latent (overwrites mis)
        out[262144 + 8192 + n * 64 + t] = acc;  // latent output
    }
    __syncthreads();
    if (t < 64) {  // t3 = relu(latent @ W3^T + b3)
        float acc = b3[t];
        const float* w = W3 + t * 64;
        for (int k = 0; k < 64; k++) acc += sv[64 + k] * w[k];
        sv[128 + t] = fmaxf(acc, 0.f);
    }
    __syncthreads();
    if (t < 64) {  // recons = t3 @ W4^T + b4 ; t5 = relu(latent @ W5^T + b5)
        float acc = b4[t];
        const float* w = W4 + t * 64;
        for (int j = 0; j < 64; j++) acc += sv[128 + j] * w[j];
        out[n * 64 + t] = acc;                  // recons output

        float acc5 = b5[t];
        const float* w5 = W5 + t * 64;
        for (int k = 0; k < 64; k++) acc5 += sv[64 + k] * w5[k];
        sv[192 + t] = fmaxf(acc5, 0.f);         // t5 (overwrites fc2)
    }
    __syncthreads();
    if (t < 2) {   // pred = t5 @ W6^T + b6
        float acc = b6[t];
        const float* w = W6 + t * 64;
        for (int j = 0; j < 64; j++) acc += sv[192 + j] * w[j];
        out[262144 + n * 2 + t] = acc;          // pred output
    }
}

// ---------------------------------------------------------------------------
// launch
// ---------------------------------------------------------------------------
extern "C" void kernel_launch(void* const* d_in, const int* in_sizes, int n_in,
                              void* d_out, int out_size) {
    const float* li    = (const float*)d_in[0];
    const float* gl    = (const float*)d_in[1];
    const float* W_up  = (const float*)d_in[2];
    const float* b_up  = (const float*)d_in[3];
    const float* W1    = (const float*)d_in[4];
    const float* b1    = (const float*)d_in[5];
    const float* W2    = (const float*)d_in[6];
    const float* b2    = (const float*)d_in[7];
    const float* W3    = (const float*)d_in[8];
    const float* b3    = (const float*)d_in[9];
    const float* W4    = (const float*)d_in[10];
    const float* b4    = (const float*)d_in[11];
    const float* W5    = (const float*)d_in[12];
    const float* b5    = (const float*)d_in[13];
    const float* W6    = (const float*)d_in[14];
    const float* b6    = (const float*)d_in[15];
    float* out = (float*)d_out;

    cudaFuncSetAttribute(k_main, cudaFuncAttributeMaxDynamicSharedMemorySize,
                         (int)MAIN_SMEM_BYTES);

    k_up<<<dim3((GDIM + 63) / 64, NB / 64), 256>>>(gl, W_up, b_up);
    k_main<<<NB, 128, MAIN_SMEM_BYTES>>>(li, W1, b1, W2, b2, W3, b3, W4, b4,
                                         W5, b5, W6, b6, out);
}

// round 9
// speedup vs baseline: 2.5707x; 1.1821x over previous
#include <cuda_runtime.h>
#include <cuda_bf16.h>

// Problem constants
#define NB    4096
#define GDIM  2016
#define S     68            // padded row stride (floats) for 64x64 matrices
#define MS    (64 * S)      // floats per matrix (4352)

// smem: 4 matrices + vectors(256) + reduction(32)
#define MAIN_SMEM_FLOATS (4 * MS + 256 + 32)
#define MAIN_SMEM_BYTES  (MAIN_SMEM_FLOATS * sizeof(float))

// Scratch for gi = gi_latent @ W_up^T + b_up   (33 MB)
__device__ float g_gi[NB * GDIM];

// ---------------------------------------------------------------------------
// tf32 helpers
// ---------------------------------------------------------------------------
__device__ __forceinline__ unsigned f2tf32_rna(float f) {
    unsigned u;
    asm("cvt.rna.tf32.f32 %0, %1;" : "=r"(u) : "f"(f));
    return u;
}

// tf32 warp MMA: D += A(16x8) @ B(8x8)
__device__ __forceinline__ void mma_tf32(float* c, unsigned a0, unsigned a1,
                                         unsigned a2, unsigned a3,
                                         unsigned b0, unsigned b1) {
    asm volatile(
        "mma.sync.aligned.m16n8k8.row.col.f32.tf32.tf32.f32 "
        "{%0,%1,%2,%3}, {%4,%5,%6,%7}, {%8,%9}, {%0,%1,%2,%3};"
        : "+f"(c[0]), "+f"(c[1]), "+f"(c[2]), "+f"(c[3])
        : "r"(a0), "r"(a1), "r"(a2), "r"(a3), "r"(b0), "r"(b1));
}

// ---------------------------------------------------------------------------
// OUT = s*(X @ Y) + a*Xres  via tensor cores. 128 threads = 4 warps, each
// warp a 32x32 tile (2x2 grid). X,Y,OUT: 64x64 stride-S fp32 in smem; OUT may
// alias X/Y (writes after barrier).
//  EC:     3xTF32 error-corrected product (fp32-quality)
//  HAS_X:  add a*xres (xres = previous step's output at C-frag positions)
//  KEEP:   also store this step's result into ores registers
// ---------------------------------------------------------------------------
template<bool EC, bool HAS_X, bool KEEP>
__device__ __forceinline__ void mm_step(const float* X, const float* Y,
                                        float* OUT, float a, float s,
                                        const float (*xres)[4][4],
                                        float (*ores)[4][4]) {
    const int t    = threadIdx.x;
    const int lane = t & 31;
    const int w    = t >> 5;
    const int gid  = lane >> 2;   // 0..7
    const int tig  = lane & 3;    // 0..3
    const int wm   = (w >> 1) * 32;
    const int wn   = (w & 1) * 32;

    float acc[2][4][4];
#pragma unroll
    for (int mt = 0; mt < 2; mt++)
#pragma unroll
        for (int nt = 0; nt < 4; nt++)
#pragma unroll
            for (int q = 0; q < 4; q++) acc[mt][nt][q] = 0.f;

#pragma unroll
    for (int ks = 0; ks < 8; ks++) {
        const int k0 = ks * 8;
        float a_f[2][4];
#pragma unroll
        for (int mt = 0; mt < 2; mt++) {
            const float* ap = X + (wm + 16 * mt + gid) * S + k0 + tig;
            a_f[mt][0] = ap[0];
            a_f[mt][1] = ap[8 * S];
            a_f[mt][2] = ap[4];
            a_f[mt][3] = ap[8 * S + 4];
        }
        float b_f[4][2];
#pragma unroll
        for (int nt = 0; nt < 4; nt++) {
            const float* bp = Y + (k0 + tig) * S + wn + 8 * nt + gid;
            b_f[nt][0] = bp[0];
            b_f[nt][1] = bp[4 * S];
        }

        if (!EC) {
#pragma unroll
            for (int mt = 0; mt < 2; mt++)
#pragma unroll
                for (int nt = 0; nt < 4; nt++)
                    mma_tf32(acc[mt][nt],
                             __float_as_uint(a_f[mt][0]), __float_as_uint(a_f[mt][1]),
                             __float_as_uint(a_f[mt][2]), __float_as_uint(a_f[mt][3]),
                             __float_as_uint(b_f[nt][0]), __float_as_uint(b_f[nt][1]));
        } else {
            unsigned ahi[2][4], alo[2][4], bhi[4][2], blo[4][2];
#pragma unroll
            for (int mt = 0; mt < 2; mt++)
#pragma unroll
                for (int q = 0; q < 4; q++) {
                    float x = a_f[mt][q];
                    unsigned h = f2tf32_rna(x);
                    ahi[mt][q] = h;
                    alo[mt][q] = __float_as_uint(x - __uint_as_float(h));
                }
#pragma unroll
            for (int nt = 0; nt < 4; nt++)
#pragma unroll
                for (int q = 0; q < 2; q++) {
                    float x = b_f[nt][q];
                    unsigned h = f2tf32_rna(x);
                    bhi[nt][q] = h;
                    blo[nt][q] = __float_as_uint(x - __uint_as_float(h));
                }
#pragma unroll
            for (int mt = 0; mt < 2; mt++)
#pragma unroll
                for (int nt = 0; nt < 4; nt++) {
                    mma_tf32(acc[mt][nt], ahi[mt][0], ahi[mt][1], ahi[mt][2], ahi[mt][3],
                             blo[nt][0], blo[nt][1]);
                    mma_tf32(acc[mt][nt], alo[mt][0], alo[mt][1], alo[mt][2], alo[mt][3],
                             bhi[nt][0], bhi[nt][1]);
                    mma_tf32(acc[mt][nt], ahi[mt][0], ahi[mt][1], ahi[mt][2], ahi[mt][3],
                             bhi[nt][0], bhi[nt][1]);
                }
        }
    }

    // epilogue: res = s*acc + a*xres (register-resident X)
    float res[2][4][4];
#pragma unroll
    for (int mt = 0; mt < 2; mt++)
#pragma unroll
        for (int nt = 0; nt < 4; nt++)
#pragma unroll
            for (int q = 0; q < 4; q++) {
                float v = s * acc[mt][nt][q];
                if (HAS_X) v += a * xres[mt][nt][q];
                res[mt][nt][q] = v;
            }
    __syncthreads();
#pragma unroll
    for (int mt = 0; mt < 2; mt++) {
        const int row = wm + 16 * mt + gid;
#pragma unroll
        for (int nt = 0; nt < 4; nt++) {
            const int col = wn + 8 * nt + 2 * tig;
            *reinterpret_cast<float2*>(OUT + row * S + col) =
                make_float2(res[mt][nt][0], res[mt][nt][1]);
            *reinterpret_cast<float2*>(OUT + (row + 8) * S + col) =
                make_float2(res[mt][nt][2], res[mt][nt][3]);
        }
    }
    if (KEEP) {
#pragma unroll
        for (int mt = 0; mt < 2; mt++)
#pragma unroll
            for (int nt = 0; nt < 4; nt++)
#pragma unroll
                for (int q = 0; q < 4; q++) ores[mt][nt][q] = res[mt][nt][q];
    }
    __syncthreads();
}

// load C-fragment positions of a smem matrix into res registers
__device__ __forceinline__ void load_res(const float* M, float (*res)[4][4]) {
    const int t    = threadIdx.x;
    const int lane = t & 31;
    const int w    = t >> 5;
    const int gid  = lane >> 2;
    const int tig  = lane & 3;
    const int wm   = (w >> 1) * 32;
    const int wn   = (w & 1) * 32;
#pragma unroll
    for (int mt = 0; mt < 2; mt++) {
        const int row = wm + 16 * mt + gid;
#pragma unroll
        for (int nt = 0; nt < 4; nt++) {
            const int col = wn + 8 * nt + 2 * tig;
            float2 x0 = *reinterpret_cast<const float2*>(M + row * S + col);
            float2 x1 = *reinterpret_cast<const float2*>(M + (row + 8) * S + col);
            res[mt][nt][0] = x0.x;
            res[mt][nt][1] = x0.y;
            res[mt][nt][2] = x1.x;
            res[mt][nt][3] = x1.y;
        }
    }
}

// ---------------------------------------------------------------------------
// Kernel 1: gi = gi_latent @ W_up^T + b_up  (proven R2 config: 256 thr, 4x4)
// ---------------------------------------------------------------------------
__global__ __launch_bounds__(256) void k_up(const float* __restrict__ gi_latent,
                                            const float* __restrict__ W_up,
                                            const float* __restrict__ b_up) {
    __shared__ float sA[64 * 64];
    __shared__ float sW[64 * 64];
    const int s0 = blockIdx.y * 64;
    const int g0 = blockIdx.x * 64;
    const int t  = threadIdx.x;

    const float4* Ag = reinterpret_cast<const float4*>(gi_latent + s0 * 64);
#pragma unroll
    for (int q = 0; q < 4; q++) {
        int e = t + q * 256;
        reinterpret_cast<float4*>(sA)[e] = Ag[e];
    }
#pragma unroll
    for (int q = 0; q < 4; q++) {
        int e   = t + q * 256;
        int row = e >> 4;
        int c4  = e & 15;
        int g   = g0 + row;
        float4 v = make_float4(0.f, 0.f, 0.f, 0.f);
        if (g < GDIM) v = reinterpret_cast<const float4*>(W_up + g * 64)[c4];
        reinterpret_cast<float4*>(sW)[e] = v;
    }
    __syncthreads();

    const int tx4 = (t & 15) * 4;
    const int ty4 = (t >> 4) * 4;
    float acc[4][4];
#pragma unroll
    for (int r = 0; r < 4; r++)
#pragma unroll
        for (int c = 0; c < 4; c++) acc[r][c] = 0.f;

#pragma unroll 8
    for (int k = 0; k < 64; k++) {
        float xv[4], wv[4];
#pragma unroll
        for (int r = 0; r < 4; r++) xv[r] = sA[(ty4 + r) * 64 + k];
#pragma unroll
        for (int c = 0; c < 4; c++) wv[c] = sW[(tx4 + c) * 64 + k];
#pragma unroll
        for (int r = 0; r < 4; r++)
#pragma unroll
            for (int c = 0; c < 4; c++) acc[r][c] += xv[r] * wv[c];
    }

#pragma unroll
    for (int r = 0; r < 4; r++)
#pragma unroll
        for (int c = 0; c < 4; c++) {
            int g = g0 + tx4 + c;
            if (g < GDIM) g_gi[(size_t)(s0 + ty4 + r) * GDIM + g] = acc[r][c] + b_up[g];
        }
}

// ---------------------------------------------------------------------------
// Kernel 2: per-sample Cayley map + MLP tail. 1 sample per 128-thread CTA.
// 9 NS iterations in tf32; final NS iteration + R in 3xTF32 error-corrected
// tensor-core matmuls (fp32-quality). Epilogue aX terms come from registers.
// ---------------------------------------------------------------------------
__global__ __launch_bounds__(128, 3) void k_main(
    const float* __restrict__ li_latent,
    const float* __restrict__ W1, const float* __restrict__ b1,
    const float* __restrict__ W2, const float* __restrict__ b2,
    const float* __restrict__ W3, const float* __restrict__ b3,
    const float* __restrict__ W4, const float* __restrict__ b4,
    const float* __restrict__ W5, const float* __restrict__ b5,
    const float* __restrict__ W6, const float* __restrict__ b6,
    float* __restrict__ out) {
    extern __shared__ float smem[];
    float* sB   = smem;               // 64 x S
    float* sZ   = smem + MS;
    float* sP   = smem + 2 * MS;
    float* sU   = smem + 3 * MS;
    float* sv   = smem + 4 * MS;      // 256 small vectors
    float* sred = smem + 4 * MS + 256;

    const int n = blockIdx.x;
    const int t = threadIdx.x;        // 0..127
    const float* gi = g_gi + (size_t)n * GDIM;

    // ---- build B = I - (A^T - A), A lower-tri from gi ----
    for (int e = t; e < GDIM; e += 128) {
        int i = (int)((1.0f + sqrtf(1.0f + 8.0f * (float)e)) * 0.5f);
        while (i * (i - 1) / 2 > e) i--;
        while ((i + 1) * i / 2 <= e) i++;
        int j   = e - i * (i - 1) / 2;
        float v = gi[e];
        sB[i * S + j] = v;    // i > j
        sB[j * S + i] = -v;
    }
    if (t < 64) sB[t * S + t] = 1.0f;
    __syncthreads();

    // ---- norms = sum(|B|) * max(|B|) over the 64x64 block (skip padding) ----
    {
        const int r  = t >> 1;
        const int c0 = (t & 1) * 32;
        float lsum = 0.f, lmax = 0.f;
#pragma unroll
        for (int q = 0; q < 8; q++) {
            float4 v = *reinterpret_cast<const float4*>(sB + r * S + c0 + q * 4);
            lsum += fabsf(v.x) + fabsf(v.y) + fabsf(v.z) + fabsf(v.w);
            lmax = fmaxf(lmax, fmaxf(fmaxf(fabsf(v.x), fabsf(v.y)),
                                     fmaxf(fabsf(v.z), fabsf(v.w))));
        }
#pragma unroll
        for (int o = 16; o; o >>= 1) {
            lsum += __shfl_xor_sync(0xFFFFFFFFu, lsum, o);
            lmax = fmaxf(lmax, __shfl_xor_sync(0xFFFFFFFFu, lmax, o));
        }
        if ((t & 31) == 0) { sred[t >> 5] = lsum; sred[4 + (t >> 5)] = lmax; }
    }
    __syncthreads();
    if (t == 0) {
        float Sm = sred[0] + sred[1] + sred[2] + sred[3];
        float Mx = fmaxf(fmaxf(sred[4], sred[5]), fmaxf(sred[6], sred[7]));
        sred[8] = 1.0f / (Sm * Mx);
    }
    __syncthreads();
    const float invn = sred[8];
    // Z0 = B^T * invn
    {
        const int r  = t >> 1;
        const int c0 = (t & 1) * 32;
        for (int c = c0; c < c0 + 32; c++)
            sZ[r * S + c] = sB[c * S + r] * invn;
    }
    __syncthreads();

    // persistent C-fragment registers
    float Pres[2][4][4], Zres[2][4][4];
    load_res(sZ, Zres);

    // ---- 9 tf32 Newton-Schulz iterations ----
#pragma unroll 1
    for (int it = 0; it < 9; it++) {
        mm_step<false, false, true >(sB, sZ, sP, 0.0f,  1.0f,  nullptr, Pres);  // P = B@Z
        mm_step<false, true,  false>(sP, sP, sU, 7.0f,  -1.0f, Pres, nullptr);  // U = 7P - P@P
        mm_step<false, true,  false>(sP, sU, sU, 15.0f, -1.0f, Pres, nullptr);  // U = 15P - P@U
        mm_step<false, true,  true >(sZ, sU, sZ, 3.25f, -0.25f, Zres, Zres);    // Z = 3.25Z - 0.25 Z@U
    }
    // ---- final NS iteration + R, 3xTF32 error-corrected (fp32 quality) ----
    mm_step<true, false, true >(sB, sZ, sP, 0.0f,  1.0f,  nullptr, Pres);
    mm_step<true, true,  false>(sP, sP, sU, 7.0f,  -1.0f, Pres, nullptr);
    mm_step<true, true,  false>(sP, sU, sU, 15.0f, -1.0f, Pres, nullptr);
    mm_step<true, true,  true >(sZ, sU, sZ, 3.25f, -0.25f, Zres, Zres);
    // R = 2Z - Z@B  -> sP
    mm_step<true, true,  false>(sZ, sB, sP, 2.0f, -1.0f, Zres, nullptr);
    const float* R = sP;

    // ---- MLP tail (threads 0..63; all threads hit the barriers) ----
    if (t < 64) sv[t] = li_latent[n * 64 + t];
    __syncthreads();

    if (t < 64) {  // mis[j] = sum_i R[i][j] * li[i]
        float acc = 0.f;
        for (int i = 0; i < 64; i++) acc += R[i * S + t] * sv[i];
        sv[64 + t] = acc;
    }
    __syncthreads();
    if (t < 64) {  // h = relu(mis @ W1^T + b1)
        float acc = b1[t];
        const float* w = W1 + t * 64;
        for (int k = 0; k < 64; k++) acc += sv[64 + k] * w[k];
        sv[128 + t] = fmaxf(acc, 0.f);
    }
    __syncthreads();
    if (t < 64) {  // fc2 = h @ W2^T + b2
        float acc = b2[t];
        const float* w = W2 + t * 64;
        for (int k = 0; k < 64; k++) acc += sv[128 + k] * w[k];
        sv[192 + t] = acc;
    }
    __syncthreads();
    if (t < 64) {  // latent[i] = sum_j R[i][j] * fc2[j]
        float acc = 0.f;
        for (int jj = 0; jj < 64; jj++) {
            int j = (t + jj) & 63;
            acc += R[t * S + j] * sv[192 + j];
        }
        sv[64 + t] = acc;                       // latent (overwrites mis)
        out[262144 + 8192 + n * 64 + t] = acc;  // latent output
    }
    __syncthreads();
    if (t < 64) {  // t3 = relu(latent @ W3^T + b3)
        float acc = b3[t];
        const float* w = W3 + t * 64;
        for (int k = 0; k < 64; k++) acc += sv[64 + k] * w[k];
        sv[128 + t] = fmaxf(acc, 0.f);
    }
    __syncthreads();
    if (t < 64) {  // recons = t3 @ W4^T + b4 ; t5 = relu(latent @ W5^T + b5)
        float acc = b4[t];
        const float* w = W4 + t * 64;
        for (int j = 0; j < 64; j++) acc += sv[128 + j] * w[j];
        out[n * 64 + t] = acc;                  // recons output

        float acc5 = b5[t];
        const float* w5 = W5 + t * 64;
        for (int k = 0; k < 64; k++) acc5 += sv[64 + k] * w5[k];
        sv[192 + t] = fmaxf(acc5, 0.f);         // t5 (overwrites fc2)
    }
    __syncthreads();
    if (t < 2) {   // pred = t5 @ W6^T + b6
        float acc = b6[t];
        const float* w = W6 + t * 64;
        for (int j = 0; j < 64; j++) acc += sv[192 + j] * w[j];
        out[262144 + n * 2 + t] = acc;          // pred output
    }
}

// ---------------------------------------------------------------------------
// launch
// ---------------------------------------------------------------------------
extern "C" void kernel_launch(void* const* d_in, const int* in_sizes, int n_in,
                              void* d_out, int out_size) {
    const float* li    = (const float*)d_in[0];
    const float* gl    = (const float*)d_in[1];
    const float* W_up  = (const float*)d_in[2];
    const float* b_up  = (const float*)d_in[3];
    const float* W1    = (const float*)d_in[4];
    const float* b1    = (const float*)d_in[5];
    const float* W2    = (const float*)d_in[6];
    const float* b2    = (const float*)d_in[7];
    const float* W3    = (const float*)d_in[8];
    const float* b3    = (const float*)d_in[9];
    const float* W4    = (const float*)d_in[10];
    const float* b4    = (const float*)d_in[11];
    const float* W5    = (const float*)d_in[12];
    const float* b5    = (const float*)d_in[13];
    const float* W6    = (const float*)d_in[14];
    const float* b6    = (const float*)d_in[15];
    float* out = (float*)d_out;

    cudaFuncSetAttribute(k_main, cudaFuncAttributeMaxDynamicSharedMemorySize,
                         (int)MAIN_SMEM_BYTES);

    k_up<<<dim3((GDIM + 63) / 64, NB / 64), 256>>>(gl, W_up, b_up);
    k_main<<<NB, 128, MAIN_SMEM_BYTES>>>(li, W1, b1, W2, b2, W3, b3, W4, b4,
                                         W5, b5, W6, b6, out);
}